// round 7
// baseline (speedup 1.0000x reference)
#include <cuda_runtime.h>
#include <math.h>
#include <stdint.h>

// Problem constants
#define BB_    8
#define LL_    512
#define HEADS_ 12
#define HS_    64
#define HID_   768
#define OD_    1536          // HEADS*2*HS
#define M1_    (BB_*LL_)     // 4096
#define BH_    (BB_*HEADS_)  // 96
#define NEG_INF_F (-3.4028234663852886e38f)

// Scratch (device globals — no allocations allowed)
__device__ uint8_t g_Af8[M1_ * HID_];     // inputs e4m3 [4096][768]
__device__ uint8_t g_WTf8[OD_ * HID_];    // W^T e4m3 [1536][768]
__device__ uint8_t g_q8[BH_ * LL_ * HS_]; // [b*h][l][d] e4m3
__device__ uint8_t g_k8[BH_ * LL_ * HS_];
__device__ float g_sin[LL_ * 32];
__device__ float g_cos[LL_ * 32];

// ---------------------------------------------------------------------------
// PTX helpers (portable ISA only — compute_103 target has no 'a' features)
// ---------------------------------------------------------------------------
__device__ __forceinline__ uint32_t smem_u32(const void* p) {
    return (uint32_t)__cvta_generic_to_shared(p);
}
__device__ __forceinline__ void cp16(uint32_t s, const void* g) {
    asm volatile("cp.async.cg.shared.global [%0], [%1], 16;\n" :: "r"(s), "l"(g));
}
#define CP_COMMIT() asm volatile("cp.async.commit_group;\n")
#define CP_WAIT0()  asm volatile("cp.async.wait_group 0;\n")
#define CP_WAIT1()  asm volatile("cp.async.wait_group 1;\n")

// cvt packs first source into the HIGH byte: d = {hi, lo}
__device__ __forceinline__ uint16_t f2e4m3x2(float hi, float lo) {
    uint16_t r;
    asm("cvt.rn.satfinite.e4m3x2.f32 %0, %1, %2;\n" : "=h"(r) : "f"(hi), "f"(lo));
    return r;
}

__device__ __forceinline__ void ldsm_x4(uint32_t* r, const void* p) {
    uint32_t a = smem_u32(p);
    asm volatile("ldmatrix.sync.aligned.m8n8.x4.shared.b16 {%0,%1,%2,%3},[%4];"
                 : "=r"(r[0]), "=r"(r[1]), "=r"(r[2]), "=r"(r[3]) : "r"(a));
}

// D += A(m16k32) * B(k32n8), e4m3 in, f32 accum
__device__ __forceinline__ void mma_fp8(float* d, const uint32_t* a, const uint32_t* b) {
    asm volatile(
        "mma.sync.aligned.m16n8k32.row.col.f32.e4m3.e4m3.f32 "
        "{%0,%1,%2,%3},{%4,%5,%6,%7},{%8,%9},{%0,%1,%2,%3};\n"
        : "+f"(d[0]), "+f"(d[1]), "+f"(d[2]), "+f"(d[3])
        : "r"(a[0]), "r"(a[1]), "r"(a[2]), "r"(a[3]), "r"(b[0]), "r"(b[1]));
}

// ---------------------------------------------------------------------------
// Kernel 0: merged prep — A->e4m3, RoPE tables, W transpose->e4m3
// ---------------------------------------------------------------------------
#define NA4_   ((M1_ * HID_) / 4)           // 786432
#define NT_    (LL_ * 32)                   // 16384
#define NPREP_ ((NA4_ + NT_ + 255) / 256)   // 3136
#define NTRB_  ((OD_ / 32) * (HID_ / 32))   // 1152

__global__ void __launch_bounds__(256)
prep_all(const float* __restrict__ A, const float* __restrict__ W) {
    const int bid = blockIdx.x;
    if (bid < NPREP_) {
        int idx = bid * 256 + threadIdx.x;
        if (idx < NA4_) {
            float4 v = ((const float4*)A)[idx];
            uint32_t lo = f2e4m3x2(v.y, v.x);
            uint32_t hi = f2e4m3x2(v.w, v.z);
            ((uint32_t*)g_Af8)[idx] = lo | (hi << 16);
        } else if (idx < NA4_ + NT_) {
            int j = idx - NA4_;
            int l = j >> 5;
            int p = j & 31;
            float inv = powf(10000.0f, -(float)p / 32.0f);
            float ang = (float)l * inv;
            g_sin[j] = sinf(ang);
            g_cos[j] = cosf(ang);
        }
        return;
    }
    __shared__ float tile[32][33];
    const int b2 = bid - NPREP_;
    const int bx = b2 % (OD_ / 32);
    const int by = b2 / (OD_ / 32);
    const int c  = threadIdx.x & 31;
    const int r4 = threadIdx.x >> 5;
    #pragma unroll
    for (int i = 0; i < 4; i++) {
        int r = r4 * 4 + i;
        tile[r][c] = W[(size_t)(by * 32 + r) * OD_ + bx * 32 + c];
    }
    __syncthreads();
    #pragma unroll
    for (int i = 0; i < 4; i++) {
        int r = r4 * 4 + i;
        g_WTf8[(size_t)(bx * 32 + r) * HID_ + by * 32 + c] =
            (uint8_t)(f2e4m3x2(0.0f, tile[c][r]) & 0xFF);
    }
}

// ---------------------------------------------------------------------------
// Kernel 1: X = A @ W + b (4096x1536, K=768), fp8 mma m16n8k32.
// 256x128 CTA tile, BK=64, 8 warps (4x2), warp tile 64x64.
// 3-stage cp.async ring. Fused bias + RoPE + e4m3 scatter epilogue.
// ---------------------------------------------------------------------------
#define A8_STRIDE    80
#define A_TILE_B     (256 * A8_STRIDE)     // 20480
#define B_TILE_B     (128 * A8_STRIDE)     // 10240
#define STAGE8       (A_TILE_B + B_TILE_B) // 30720
#define G1_DSMEM     (3 * STAGE8)          // 92160

__global__ void __launch_bounds__(256, 1)
gemm1_fp8(const float* __restrict__ bias) {
    extern __shared__ uint8_t sm8[];

    const int t    = threadIdx.x;
    const int lane = t & 31;
    const int warp = t >> 5;
    const int g    = lane >> 2;
    const int tig  = lane & 3;
    const int wm   = warp >> 1;     // 0..3 (64 rows each)
    const int wn   = warp & 1;      // 0..1 (64 cols each)
    const int m0   = blockIdx.y * 256;
    const int n0   = blockIdx.x * 128;

    float acc[4][8][4];   // [mt 16-row][n8][4]
    #pragma unroll
    for (int mt = 0; mt < 4; mt++)
        #pragma unroll
        for (int j = 0; j < 8; j++)
            #pragma unroll
            for (int c = 0; c < 4; c++) acc[mt][j][c] = 0.0f;

    auto load_tile = [&](int buf, int k0) {
        uint8_t* as = sm8 + buf * STAGE8;
        uint8_t* bs = as + A_TILE_B;
        #pragma unroll
        for (int i = 0; i < 4; i++) {          // A: 1024 x 16B chunks
            int ch = t + 256 * i;
            int r = ch >> 2;
            int cc = (ch & 3) * 16;
            cp16(smem_u32(as + r * A8_STRIDE + cc),
                 g_Af8 + (size_t)(m0 + r) * HID_ + k0 + cc);
        }
        #pragma unroll
        for (int i = 0; i < 2; i++) {          // B: 512 x 16B chunks
            int ch = t + 256 * i;
            int r = ch >> 2;
            int cc = (ch & 3) * 16;
            cp16(smem_u32(bs + r * A8_STRIDE + cc),
                 g_WTf8 + (size_t)(n0 + r) * HID_ + k0 + cc);
        }
        CP_COMMIT();
    };

    load_tile(0, 0);
    load_tile(1, 64);

    const int a_row  = lane & 15;
    const int a_coff = (lane >> 4) * 16;
    const int b_row  = (lane & 7) + 8 * (lane >> 4);
    const int b_coff = 16 * ((lane >> 3) & 1);
    const int aoff   = (wm * 64 + a_row) * A8_STRIDE + a_coff;
    const int boff   = (wn * 64 + b_row) * A8_STRIDE + b_coff;

    for (int kt = 0; kt < 12; kt++) {
        const int buf = kt % 3;
        CP_WAIT1();
        __syncthreads();
        if (kt + 2 < 12) load_tile((kt + 2) % 3, (kt + 2) * 64);
        else             CP_COMMIT();   // keep group count uniform for WAIT1

        const uint8_t* as = sm8 + buf * STAGE8;
        const uint8_t* bs = as + A_TILE_B;

        #pragma unroll
        for (int kk = 0; kk < 2; kk++) {
            const int k32 = kk * 32;
            uint32_t af[4][4];
            #pragma unroll
            for (int mt = 0; mt < 4; mt++)
                ldsm_x4(af[mt], as + aoff + mt * 16 * A8_STRIDE + k32);
            #pragma unroll
            for (int nt = 0; nt < 4; nt++) {
                uint32_t bf[4];
                ldsm_x4(bf, bs + boff + nt * 16 * A8_STRIDE + k32);
                #pragma unroll
                for (int mt = 0; mt < 4; mt++) {
                    mma_fp8(acc[mt][2 * nt],     af[mt], &bf[0]);
                    mma_fp8(acc[mt][2 * nt + 1], af[mt], &bf[2]);
                }
            }
        }
    }

    // Epilogue: bias + RoPE + e4m3 scatter to g_q8/g_k8 ([b*h][l][d])
    #pragma unroll
    for (int mt = 0; mt < 4; mt++) {
        #pragma unroll
        for (int half = 0; half < 2; half++) {
            const int m  = m0 + wm * 64 + mt * 16 + g + half * 8;
            const int l  = m & (LL_ - 1);
            const int b_ = m >> 9;
            #pragma unroll
            for (int j = 0; j < 8; j++) {
                const int n = n0 + wn * 64 + j * 8 + 2 * tig;   // even col
                float e = acc[mt][j][half * 2 + 0] + bias[n];
                float o = acc[mt][j][half * 2 + 1] + bias[n + 1];
                const int h  = n >> 7;
                const int qk = (n >> 6) & 1;
                const int d  = n & 63;
                const int p  = d >> 1;
                const float s  = g_sin[l * 32 + p];
                const float co = g_cos[l * 32 + p];
                uint16_t v = f2e4m3x2(e * s + o * co, e * co - o * s);
                uint8_t* dst = (qk ? g_k8 : g_q8)
                    + ((size_t)(b_ * HEADS_ + h) * LL_ + l) * HS_ + d;
                *(uint16_t*)dst = v;
            }
        }
    }
}

// ---------------------------------------------------------------------------
// Kernel 2: logits = (q.k)/8, masked; fp8 mma (R5 version — measured 21.6us).
// 64x64 tile, 4 warps (2x2), warp tile 32x32, K=64 (2 k32 steps).
// ---------------------------------------------------------------------------
#define QK8_STRIDE 80

__global__ void __launch_bounds__(128)
attn_logits_fp8(const int* __restrict__ am, float* __restrict__ out) {
    const int bh = blockIdx.z;
    const int tm = blockIdx.y;
    const int tn = blockIdx.x;
    const int t  = threadIdx.x;
    const int b_ = bh / HEADS_;
    const int m0 = tm * 64;
    const int n0 = tn * 64;
    float* obase = out + (size_t)bh * LL_ * LL_;

    if (tm > tn) {
        const float4 nv = make_float4(NEG_INF_F, NEG_INF_F, NEG_INF_F, NEG_INF_F);
        #pragma unroll
        for (int i = t; i < 1024; i += 128) {
            int r = i >> 4;
            int c = (i & 15) * 4;
            *(float4*)&obase[(size_t)(m0 + r) * LL_ + n0 + c] = nv;
        }
        return;
    }

    __shared__ uint8_t Qs[64 * QK8_STRIDE];
    __shared__ uint8_t Ks[64 * QK8_STRIDE];
    __shared__ int rmv[64], cmv[64];

    const uint8_t* qb = g_q8 + ((size_t)bh * LL_ + m0) * HS_;
    const uint8_t* kb = g_k8 + ((size_t)bh * LL_ + n0) * HS_;

    #pragma unroll
    for (int i = 0; i < 2; i++) {
        int ch = t + 128 * i;
        int r = ch >> 2;
        int c = (ch & 3) * 16;
        cp16(smem_u32(&Qs[r * QK8_STRIDE + c]), qb + r * HS_ + c);
        cp16(smem_u32(&Ks[r * QK8_STRIDE + c]), kb + r * HS_ + c);
    }
    CP_COMMIT();
    if (t < 64)       rmv[t]      = am[b_ * LL_ + m0 + t];
    else if (t < 128) cmv[t - 64] = am[b_ * LL_ + n0 + (t - 64)];
    CP_WAIT0();
    __syncthreads();

    const int lane = t & 31;
    const int warp = t >> 5;
    const int g    = lane >> 2;
    const int tig  = lane & 3;
    const int wm   = warp >> 1;
    const int wn   = warp & 1;

    float acc[2][4][4];
    #pragma unroll
    for (int mt = 0; mt < 2; mt++)
        #pragma unroll
        for (int j = 0; j < 4; j++)
            #pragma unroll
            for (int c = 0; c < 4; c++) acc[mt][j][c] = 0.0f;

    const int a_row  = lane & 15;
    const int a_coff = (lane >> 4) * 16;
    const int b_row  = (lane & 7) + 8 * (lane >> 4);
    const int b_coff = 16 * ((lane >> 3) & 1);

    #pragma unroll
    for (int kk = 0; kk < 2; kk++) {
        const int k32 = kk * 32;
        uint32_t qf[2][4];
        #pragma unroll
        for (int mt = 0; mt < 2; mt++) {
            int row = wm * 32 + mt * 16 + a_row;
            ldsm_x4(qf[mt], &Qs[row * QK8_STRIDE + k32 + a_coff]);
        }
        #pragma unroll
        for (int nt = 0; nt < 2; nt++) {
            uint32_t kf[4];
            int row = wn * 32 + nt * 16 + b_row;
            ldsm_x4(kf, &Ks[row * QK8_STRIDE + k32 + b_coff]);
            mma_fp8(acc[0][2 * nt],     qf[0], &kf[0]);
            mma_fp8(acc[0][2 * nt + 1], qf[0], &kf[2]);
            mma_fp8(acc[1][2 * nt],     qf[1], &kf[0]);
            mma_fp8(acc[1][2 * nt + 1], qf[1], &kf[2]);
        }
    }

    #pragma unroll
    for (int mt = 0; mt < 2; mt++) {
        #pragma unroll
        for (int half = 0; half < 2; half++) {
            const int mi = wm * 32 + mt * 16 + g + half * 8;
            const int m  = m0 + mi;
            const bool rok = (rmv[mi] != 0);
            #pragma unroll
            for (int j = 0; j < 4; j++) {
                const int ni = wn * 32 + j * 8 + 2 * tig;
                const int n  = n0 + ni;
                float x0 = acc[mt][j][half * 2 + 0] * 0.125f;
                float x1 = acc[mt][j][half * 2 + 1] * 0.125f;
                if (m > n     || !rok || cmv[ni]     == 0) x0 = NEG_INF_F;
                if (m > n + 1 || !rok || cmv[ni + 1] == 0) x1 = NEG_INF_F;
                *(float2*)&obase[(size_t)m * LL_ + n] = make_float2(x0, x1);
            }
        }
    }
}

// ---------------------------------------------------------------------------
// Entry point
// ---------------------------------------------------------------------------
extern "C" void kernel_launch(void* const* d_in, const int* in_sizes, int n_in,
                              void* d_out, int out_size) {
    const float* inputs = (const float*)d_in[0];  // [8,512,768]
    const float* W      = (const float*)d_in[1];  // [768,1536]
    const float* bias   = (const float*)d_in[2];  // [1536]
    const int*   amask  = (const int*)d_in[3];    // [8,512]
    float* out = (float*)d_out;                   // [8,12,512,512]

    cudaFuncSetAttribute(gemm1_fp8,
                         cudaFuncAttributeMaxDynamicSharedMemorySize, G1_DSMEM);

    prep_all<<<NPREP_ + NTRB_, 256>>>(inputs, W);
    gemm1_fp8<<<dim3(OD_ / 128, M1_ / 256), 256, G1_DSMEM>>>(bias);
    attn_logits_fp8<<<dim3(LL_ / 64, LL_ / 64, BH_), 128>>>(amask, out);
}

// round 9
// speedup vs baseline: 1.2676x; 1.2676x over previous
#include <cuda_runtime.h>
#include <math.h>
#include <stdint.h>

// Problem constants
#define BB_    8
#define LL_    512
#define HEADS_ 12
#define HS_    64
#define HID_   768
#define OD_    1536          // HEADS*2*HS
#define M1_    (BB_*LL_)     // 4096
#define BH_    (BB_*HEADS_)  // 96
#define NEG_INF_F (-3.4028234663852886e38f)

// Scratch (device globals — no allocations allowed)
__device__ uint8_t g_Af8[M1_ * HID_];     // inputs e4m3 [4096][768]
__device__ uint8_t g_WTf8[OD_ * HID_];    // W^T e4m3 [1536][768]
__device__ uint8_t g_q8[BH_ * LL_ * HS_]; // [b*h][l][d] e4m3
__device__ uint8_t g_k8[BH_ * LL_ * HS_];
__device__ float g_sin[LL_ * 32];
__device__ float g_cos[LL_ * 32];

// ---------------------------------------------------------------------------
// PTX helpers (portable ISA only — compute_103 target has no 'a' features)
// ---------------------------------------------------------------------------
__device__ __forceinline__ uint32_t smem_u32(const void* p) {
    return (uint32_t)__cvta_generic_to_shared(p);
}
__device__ __forceinline__ void cp16(uint32_t s, const void* g) {
    asm volatile("cp.async.cg.shared.global [%0], [%1], 16;\n" :: "r"(s), "l"(g));
}
#define CP_COMMIT() asm volatile("cp.async.commit_group;\n")
#define CP_WAIT0()  asm volatile("cp.async.wait_group 0;\n")
#define CP_WAIT2()  asm volatile("cp.async.wait_group 2;\n")

// cvt packs first source into the HIGH byte: d = {hi, lo}
__device__ __forceinline__ uint16_t f2e4m3x2(float hi, float lo) {
    uint16_t r;
    asm("cvt.rn.satfinite.e4m3x2.f32 %0, %1, %2;\n" : "=h"(r) : "f"(hi), "f"(lo));
    return r;
}

__device__ __forceinline__ void ldsm_x4(uint32_t* r, const void* p) {
    uint32_t a = smem_u32(p);
    asm volatile("ldmatrix.sync.aligned.m8n8.x4.shared.b16 {%0,%1,%2,%3},[%4];"
                 : "=r"(r[0]), "=r"(r[1]), "=r"(r[2]), "=r"(r[3]) : "r"(a));
}

// D += A(m16k32) * B(k32n8), e4m3 in, f32 accum
__device__ __forceinline__ void mma_fp8(float* d, const uint32_t* a, const uint32_t* b) {
    asm volatile(
        "mma.sync.aligned.m16n8k32.row.col.f32.e4m3.e4m3.f32 "
        "{%0,%1,%2,%3},{%4,%5,%6,%7},{%8,%9},{%0,%1,%2,%3};\n"
        : "+f"(d[0]), "+f"(d[1]), "+f"(d[2]), "+f"(d[3])
        : "r"(a[0]), "r"(a[1]), "r"(a[2]), "r"(a[3]), "r"(b[0]), "r"(b[1]));
}

// Streaming (evict-first) stores for write-once output
__device__ __forceinline__ void stg_cs_f2(float* p, float x, float y) {
    asm volatile("st.global.cs.v2.f32 [%0], {%1,%2};\n" :: "l"(p), "f"(x), "f"(y) : "memory");
}
__device__ __forceinline__ void stg_cs_f4(float* p, float4 v) {
    asm volatile("st.global.cs.v4.f32 [%0], {%1,%2,%3,%4};\n"
                 :: "l"(p), "f"(v.x), "f"(v.y), "f"(v.z), "f"(v.w) : "memory");
}

// ---------------------------------------------------------------------------
// Kernel 0: merged prep — A->e4m3, RoPE tables, W transpose->e4m3
// (measured 7.3us; saves a launch vs separate kernels)
// ---------------------------------------------------------------------------
#define NA4_   ((M1_ * HID_) / 4)           // 786432
#define NT_    (LL_ * 32)                   // 16384
#define NPREP_ ((NA4_ + NT_ + 255) / 256)   // 3136
#define NTRB_  ((OD_ / 32) * (HID_ / 32))   // 1152

__global__ void __launch_bounds__(256)
prep_all(const float* __restrict__ A, const float* __restrict__ W) {
    const int bid = blockIdx.x;
    if (bid < NPREP_) {
        int idx = bid * 256 + threadIdx.x;
        if (idx < NA4_) {
            float4 v = ((const float4*)A)[idx];
            uint32_t lo = f2e4m3x2(v.y, v.x);
            uint32_t hi = f2e4m3x2(v.w, v.z);
            ((uint32_t*)g_Af8)[idx] = lo | (hi << 16);
        } else if (idx < NA4_ + NT_) {
            int j = idx - NA4_;
            int l = j >> 5;
            int p = j & 31;
            float inv = powf(10000.0f, -(float)p / 32.0f);
            float ang = (float)l * inv;
            g_sin[j] = sinf(ang);
            g_cos[j] = cosf(ang);
        }
        return;
    }
    __shared__ float tile[32][33];
    const int b2 = bid - NPREP_;
    const int bx = b2 % (OD_ / 32);
    const int by = b2 / (OD_ / 32);
    const int c  = threadIdx.x & 31;
    const int r4 = threadIdx.x >> 5;
    #pragma unroll
    for (int i = 0; i < 4; i++) {
        int r = r4 * 4 + i;
        tile[r][c] = W[(size_t)(by * 32 + r) * OD_ + bx * 32 + c];
    }
    __syncthreads();
    #pragma unroll
    for (int i = 0; i < 4; i++) {
        int r = r4 * 4 + i;
        g_WTf8[(size_t)(bx * 32 + r) * HID_ + by * 32 + c] =
            (uint8_t)(f2e4m3x2(0.0f, tile[c][r]) & 0xFF);
    }
}

// ---------------------------------------------------------------------------
// Kernel 1: X = A @ W + b (4096x1536, K=768), fp8 mma m16n8k32.
// EXACT R5 configuration (measured-best): 128x128 block, BK=64, 8 warps (4x2),
// warp tile 32x64, 4-stage cp.async ring, 2 CTAs/SM, plain loop order.
// ---------------------------------------------------------------------------
#define A8_STRIDE   80
#define TILE8_BYTES (128 * A8_STRIDE)      // 10240
#define STAGE8      (2 * TILE8_BYTES)      // 20480
#define G1_DSMEM    (4 * STAGE8)           // 81920

__global__ void __launch_bounds__(256, 2)
gemm1_fp8(const float* __restrict__ bias) {
    extern __shared__ uint8_t sm8[];

    const int t    = threadIdx.x;
    const int lane = t & 31;
    const int warp = t >> 5;
    const int g    = lane >> 2;
    const int tig  = lane & 3;
    const int wm   = warp >> 1;     // 0..3
    const int wn   = warp & 1;      // 0..1
    const int m0   = blockIdx.y * 128;
    const int n0   = blockIdx.x * 128;

    float acc[2][8][4];
    #pragma unroll
    for (int mt = 0; mt < 2; mt++)
        #pragma unroll
        for (int j = 0; j < 8; j++)
            #pragma unroll
            for (int c = 0; c < 4; c++) acc[mt][j][c] = 0.0f;

    auto load_tile = [&](int buf, int k0) {
        uint8_t* as = sm8 + buf * STAGE8;
        uint8_t* bs = as + TILE8_BYTES;
        #pragma unroll
        for (int i = 0; i < 2; i++) {          // A: 512 x 16B chunks
            int ch = t + 256 * i;
            int r = ch >> 2;
            int cc = (ch & 3) * 16;
            cp16(smem_u32(as + r * A8_STRIDE + cc),
                 g_Af8 + (size_t)(m0 + r) * HID_ + k0 + cc);
        }
        #pragma unroll
        for (int i = 0; i < 2; i++) {          // B: 512 x 16B chunks
            int ch = t + 256 * i;
            int r = ch >> 2;
            int cc = (ch & 3) * 16;
            cp16(smem_u32(bs + r * A8_STRIDE + cc),
                 g_WTf8 + (size_t)(n0 + r) * HID_ + k0 + cc);
        }
        CP_COMMIT();
    };

    load_tile(0, 0);
    load_tile(1, 64);
    load_tile(2, 128);

    const int a_row  = lane & 15;
    const int a_coff = (lane >> 4) * 16;
    const int b_row  = (lane & 7) + 8 * (lane >> 4);
    const int b_coff = 16 * ((lane >> 3) & 1);

    for (int kt = 0; kt < 12; kt++) {
        const int buf = kt & 3;
        CP_WAIT2();
        __syncthreads();
        if (kt + 3 < 12) load_tile((kt + 3) & 3, (kt + 3) * 64);
        else             CP_COMMIT();   // keep group count uniform for WAIT2

        const uint8_t* as = sm8 + buf * STAGE8;
        const uint8_t* bs = as + TILE8_BYTES;

        #pragma unroll
        for (int kk = 0; kk < 2; kk++) {
            const int k32 = kk * 32;
            uint32_t af[2][4];
            #pragma unroll
            for (int mt = 0; mt < 2; mt++) {
                int row = wm * 32 + mt * 16 + a_row;
                ldsm_x4(af[mt], as + row * A8_STRIDE + k32 + a_coff);
            }
            #pragma unroll
            for (int nt = 0; nt < 4; nt++) {
                uint32_t bf[4];
                int row = wn * 64 + nt * 16 + b_row;
                ldsm_x4(bf, bs + row * A8_STRIDE + k32 + b_coff);
                mma_fp8(acc[0][2 * nt],     af[0], &bf[0]);
                mma_fp8(acc[0][2 * nt + 1], af[0], &bf[2]);
                mma_fp8(acc[1][2 * nt],     af[1], &bf[0]);
                mma_fp8(acc[1][2 * nt + 1], af[1], &bf[2]);
            }
        }
    }

    // Epilogue: bias + RoPE + e4m3 scatter to g_q8/g_k8 ([b*h][l][d])
    #pragma unroll
    for (int mt = 0; mt < 2; mt++) {
        #pragma unroll
        for (int half = 0; half < 2; half++) {
            const int m  = m0 + wm * 32 + mt * 16 + g + half * 8;
            const int l  = m & (LL_ - 1);
            const int b_ = m >> 9;
            #pragma unroll
            for (int j = 0; j < 8; j++) {
                const int n = n0 + wn * 64 + j * 8 + 2 * tig;   // even col
                float e = acc[mt][j][half * 2 + 0] + bias[n];
                float o = acc[mt][j][half * 2 + 1] + bias[n + 1];
                const int h  = n >> 7;
                const int qk = (n >> 6) & 1;
                const int d  = n & 63;
                const int p  = d >> 1;
                const float s  = g_sin[l * 32 + p];
                const float co = g_cos[l * 32 + p];
                uint16_t v = f2e4m3x2(e * s + o * co, e * co - o * s);
                uint8_t* dst = (qk ? g_k8 : g_q8)
                    + ((size_t)(b_ * HEADS_ + h) * LL_ + l) * HS_ + d;
                *(uint16_t*)dst = v;
            }
        }
    }
}

// ---------------------------------------------------------------------------
// Kernel 2: logits = (q.k)/8, masked; fp8 mma (R5 structure, 21.6us) with
// streaming (evict-first) output stores — output is write-once.
// 64x64 tile, 4 warps (2x2), warp tile 32x32, K=64 (2 k32 steps).
// ---------------------------------------------------------------------------
#define QK8_STRIDE 80

__global__ void __launch_bounds__(128)
attn_logits_fp8(const int* __restrict__ am, float* __restrict__ out) {
    const int bh = blockIdx.z;
    const int tm = blockIdx.y;
    const int tn = blockIdx.x;
    const int t  = threadIdx.x;
    const int b_ = bh / HEADS_;
    const int m0 = tm * 64;
    const int n0 = tn * 64;
    float* obase = out + (size_t)bh * LL_ * LL_;

    if (tm > tn) {
        const float4 nv = make_float4(NEG_INF_F, NEG_INF_F, NEG_INF_F, NEG_INF_F);
        #pragma unroll
        for (int i = t; i < 1024; i += 128) {
            int r = i >> 4;
            int c = (i & 15) * 4;
            stg_cs_f4(&obase[(size_t)(m0 + r) * LL_ + n0 + c], nv);
        }
        return;
    }

    __shared__ uint8_t Qs[64 * QK8_STRIDE];
    __shared__ uint8_t Ks[64 * QK8_STRIDE];
    __shared__ int rmv[64], cmv[64];

    const uint8_t* qb = g_q8 + ((size_t)bh * LL_ + m0) * HS_;
    const uint8_t* kb = g_k8 + ((size_t)bh * LL_ + n0) * HS_;

    #pragma unroll
    for (int i = 0; i < 2; i++) {
        int ch = t + 128 * i;
        int r = ch >> 2;
        int c = (ch & 3) * 16;
        cp16(smem_u32(&Qs[r * QK8_STRIDE + c]), qb + r * HS_ + c);
        cp16(smem_u32(&Ks[r * QK8_STRIDE + c]), kb + r * HS_ + c);
    }
    CP_COMMIT();
    if (t < 64)       rmv[t]      = am[b_ * LL_ + m0 + t];
    else if (t < 128) cmv[t - 64] = am[b_ * LL_ + n0 + (t - 64)];
    CP_WAIT0();
    __syncthreads();

    const int lane = t & 31;
    const int warp = t >> 5;
    const int g    = lane >> 2;
    const int tig  = lane & 3;
    const int wm   = warp >> 1;
    const int wn   = warp & 1;

    float acc[2][4][4];
    #pragma unroll
    for (int mt = 0; mt < 2; mt++)
        #pragma unroll
        for (int j = 0; j < 4; j++)
            #pragma unroll
            for (int c = 0; c < 4; c++) acc[mt][j][c] = 0.0f;

    const int a_row  = lane & 15;
    const int a_coff = (lane >> 4) * 16;
    const int b_row  = (lane & 7) + 8 * (lane >> 4);
    const int b_coff = 16 * ((lane >> 3) & 1);

    #pragma unroll
    for (int kk = 0; kk < 2; kk++) {
        const int k32 = kk * 32;
        uint32_t qf[2][4];
        #pragma unroll
        for (int mt = 0; mt < 2; mt++) {
            int row = wm * 32 + mt * 16 + a_row;
            ldsm_x4(qf[mt], &Qs[row * QK8_STRIDE + k32 + a_coff]);
        }
        #pragma unroll
        for (int nt = 0; nt < 2; nt++) {
            uint32_t kf[4];
            int row = wn * 32 + nt * 16 + b_row;
            ldsm_x4(kf, &Ks[row * QK8_STRIDE + k32 + b_coff]);
            mma_fp8(acc[0][2 * nt],     qf[0], &kf[0]);
            mma_fp8(acc[0][2 * nt + 1], qf[0], &kf[2]);
            mma_fp8(acc[1][2 * nt],     qf[1], &kf[0]);
            mma_fp8(acc[1][2 * nt + 1], qf[1], &kf[2]);
        }
    }

    #pragma unroll
    for (int mt = 0; mt < 2; mt++) {
        #pragma unroll
        for (int half = 0; half < 2; half++) {
            const int mi = wm * 32 + mt * 16 + g + half * 8;
            const int m  = m0 + mi;
            const bool rok = (rmv[mi] != 0);
            #pragma unroll
            for (int j = 0; j < 4; j++) {
                const int ni = wn * 32 + j * 8 + 2 * tig;
                const int n  = n0 + ni;
                float x0 = acc[mt][j][half * 2 + 0] * 0.125f;
                float x1 = acc[mt][j][half * 2 + 1] * 0.125f;
                if (m > n     || !rok || cmv[ni]     == 0) x0 = NEG_INF_F;
                if (m > n + 1 || !rok || cmv[ni + 1] == 0) x1 = NEG_INF_F;
                stg_cs_f2(&obase[(size_t)m * LL_ + n], x0, x1);
            }
        }
    }
}

// ---------------------------------------------------------------------------
// Entry point
// ---------------------------------------------------------------------------
extern "C" void kernel_launch(void* const* d_in, const int* in_sizes, int n_in,
                              void* d_out, int out_size) {
    const float* inputs = (const float*)d_in[0];  // [8,512,768]
    const float* W      = (const float*)d_in[1];  // [768,1536]
    const float* bias   = (const float*)d_in[2];  // [1536]
    const int*   amask  = (const int*)d_in[3];    // [8,512]
    float* out = (float*)d_out;                   // [8,12,512,512]

    cudaFuncSetAttribute(gemm1_fp8,
                         cudaFuncAttributeMaxDynamicSharedMemorySize, G1_DSMEM);

    prep_all<<<NPREP_ + NTRB_, 256>>>(inputs, W);
    gemm1_fp8<<<dim3(OD_ / 128, M1_ / 128), 256, G1_DSMEM>>>(bias);
    attn_logits_fp8<<<dim3(LL_ / 64, LL_ / 64, BH_), 128>>>(amask, out);
}

// round 10
// speedup vs baseline: 1.2693x; 1.0014x over previous
#include <cuda_runtime.h>
#include <math.h>
#include <stdint.h>

// Problem constants
#define BB_    8
#define LL_    512
#define HEADS_ 12
#define HS_    64
#define HID_   768
#define OD_    1536          // HEADS*2*HS
#define M1_    (BB_*LL_)     // 4096
#define BH_    (BB_*HEADS_)  // 96
#define NEG_INF_F (-3.4028234663852886e38f)

// Scratch (device globals — no allocations allowed)
__device__ uint8_t g_Af8[M1_ * HID_];     // inputs e4m3 [4096][768]
__device__ uint8_t g_WTf8[OD_ * HID_];    // W^T e4m3 [1536][768]
__device__ uint8_t g_q8[BH_ * LL_ * HS_]; // [b*h][l][d] e4m3
__device__ uint8_t g_k8[BH_ * LL_ * HS_];
__device__ float g_sin[LL_ * 32];
__device__ float g_cos[LL_ * 32];

// ---------------------------------------------------------------------------
// PTX helpers (portable ISA only — compute_103 target has no 'a' features)
// ---------------------------------------------------------------------------
__device__ __forceinline__ uint32_t smem_u32(const void* p) {
    return (uint32_t)__cvta_generic_to_shared(p);
}
__device__ __forceinline__ void cp16(uint32_t s, const void* g) {
    asm volatile("cp.async.cg.shared.global [%0], [%1], 16;\n" :: "r"(s), "l"(g));
}
#define CP_COMMIT() asm volatile("cp.async.commit_group;\n")
#define CP_WAIT0()  asm volatile("cp.async.wait_group 0;\n")
#define CP_WAIT2()  asm volatile("cp.async.wait_group 2;\n")

// cvt packs first source into the HIGH byte: d = {hi, lo}
__device__ __forceinline__ uint16_t f2e4m3x2(float hi, float lo) {
    uint16_t r;
    asm("cvt.rn.satfinite.e4m3x2.f32 %0, %1, %2;\n" : "=h"(r) : "f"(hi), "f"(lo));
    return r;
}

__device__ __forceinline__ void ldsm_x4(uint32_t* r, const void* p) {
    uint32_t a = smem_u32(p);
    asm volatile("ldmatrix.sync.aligned.m8n8.x4.shared.b16 {%0,%1,%2,%3},[%4];"
                 : "=r"(r[0]), "=r"(r[1]), "=r"(r[2]), "=r"(r[3]) : "r"(a));
}

// D += A(m16k32) * B(k32n8), e4m3 in, f32 accum
__device__ __forceinline__ void mma_fp8(float* d, const uint32_t* a, const uint32_t* b) {
    asm volatile(
        "mma.sync.aligned.m16n8k32.row.col.f32.e4m3.e4m3.f32 "
        "{%0,%1,%2,%3},{%4,%5,%6,%7},{%8,%9},{%0,%1,%2,%3};\n"
        : "+f"(d[0]), "+f"(d[1]), "+f"(d[2]), "+f"(d[3])
        : "r"(a[0]), "r"(a[1]), "r"(a[2]), "r"(a[3]), "r"(b[0]), "r"(b[1]));
}

// Streaming (evict-first) stores for write-once output
__device__ __forceinline__ void stg_cs_f2(float* p, float x, float y) {
    asm volatile("st.global.cs.v2.f32 [%0], {%1,%2};\n" :: "l"(p), "f"(x), "f"(y) : "memory");
}
__device__ __forceinline__ void stg_cs_f4(float* p, float4 v) {
    asm volatile("st.global.cs.v4.f32 [%0], {%1,%2,%3,%4};\n"
                 :: "l"(p), "f"(v.x), "f"(v.y), "f"(v.z), "f"(v.w) : "memory");
}

// ---------------------------------------------------------------------------
// Kernel 0: merged prep — A->e4m3 (MLP=4), RoPE tables, W transpose->e4m3
// ---------------------------------------------------------------------------
#define NA4_   ((M1_ * HID_) / 4)           // 786432 float4s of A
#define NAB_   (NA4_ / 1024)                // 768 A-convert blocks (1024 f4 each)
#define NT_    (LL_ * 32)                   // 16384 table entries
#define NTB_   (NT_ / 256)                  // 64 table blocks
#define NTRB_  ((OD_ / 32) * (HID_ / 32))   // 1152 transpose blocks

__global__ void __launch_bounds__(256)
prep_all(const float* __restrict__ A, const float* __restrict__ W) {
    const int bid = blockIdx.x;
    const int tid = threadIdx.x;
    if (bid < NAB_) {
        // A convert: block owns 1024 consecutive float4s; 4 strided loads/thread
        const int base = bid * 1024 + tid;
        float4 v0 = ((const float4*)A)[base];
        float4 v1 = ((const float4*)A)[base + 256];
        float4 v2 = ((const float4*)A)[base + 512];
        float4 v3 = ((const float4*)A)[base + 768];
        uint32_t r0 = (uint32_t)f2e4m3x2(v0.y, v0.x) | ((uint32_t)f2e4m3x2(v0.w, v0.z) << 16);
        uint32_t r1 = (uint32_t)f2e4m3x2(v1.y, v1.x) | ((uint32_t)f2e4m3x2(v1.w, v1.z) << 16);
        uint32_t r2 = (uint32_t)f2e4m3x2(v2.y, v2.x) | ((uint32_t)f2e4m3x2(v2.w, v2.z) << 16);
        uint32_t r3 = (uint32_t)f2e4m3x2(v3.y, v3.x) | ((uint32_t)f2e4m3x2(v3.w, v3.z) << 16);
        ((uint32_t*)g_Af8)[base]       = r0;
        ((uint32_t*)g_Af8)[base + 256] = r1;
        ((uint32_t*)g_Af8)[base + 512] = r2;
        ((uint32_t*)g_Af8)[base + 768] = r3;
        return;
    }
    if (bid < NAB_ + NTB_) {
        int j = (bid - NAB_) * 256 + tid;
        int l = j >> 5;
        int p = j & 31;
        float inv = powf(10000.0f, -(float)p / 32.0f);
        float ang = (float)l * inv;
        g_sin[j] = sinf(ang);
        g_cos[j] = cosf(ang);
        return;
    }
    // W [768][1536] fp32 -> g_WTf8 [1536][768] e4m3, 32x32 tiles, 4B stores
    __shared__ float tile[32][33];
    const int b2 = bid - NAB_ - NTB_;
    const int bx = b2 % (OD_ / 32);
    const int by = b2 / (OD_ / 32);
    {
        const int c  = tid & 31;
        const int r4 = tid >> 5;
        #pragma unroll
        for (int i = 0; i < 4; i++) {
            int r = r4 * 4 + i;
            tile[r][c] = W[(size_t)(by * 32 + r) * OD_ + bx * 32 + c];
        }
    }
    __syncthreads();
    {
        const int r  = tid >> 3;        // 0..31 output row (N dim)
        const int cg = tid & 7;         // 0..7 group of 4 K-cols
        uint32_t val = 0;
        #pragma unroll
        for (int j = 0; j < 4; j++) {
            uint32_t b = f2e4m3x2(0.0f, tile[cg * 4 + j][r]) & 0xFF;
            val |= b << (8 * j);
        }
        *(uint32_t*)&g_WTf8[(size_t)(bx * 32 + r) * HID_ + by * 32 + cg * 4] = val;
    }
}

// ---------------------------------------------------------------------------
// Kernel 1: X = A @ W + b (4096x1536, K=768), fp8 mma m16n8k32.
// FROZEN R5/R8 configuration (measured-best).
// ---------------------------------------------------------------------------
#define A8_STRIDE   80
#define TILE8_BYTES (128 * A8_STRIDE)      // 10240
#define STAGE8      (2 * TILE8_BYTES)      // 20480
#define G1_DSMEM    (4 * STAGE8)           // 81920

__global__ void __launch_bounds__(256, 2)
gemm1_fp8(const float* __restrict__ bias) {
    extern __shared__ uint8_t sm8[];

    const int t    = threadIdx.x;
    const int lane = t & 31;
    const int warp = t >> 5;
    const int g    = lane >> 2;
    const int tig  = lane & 3;
    const int wm   = warp >> 1;     // 0..3
    const int wn   = warp & 1;      // 0..1
    const int m0   = blockIdx.y * 128;
    const int n0   = blockIdx.x * 128;

    float acc[2][8][4];
    #pragma unroll
    for (int mt = 0; mt < 2; mt++)
        #pragma unroll
        for (int j = 0; j < 8; j++)
            #pragma unroll
            for (int c = 0; c < 4; c++) acc[mt][j][c] = 0.0f;

    auto load_tile = [&](int buf, int k0) {
        uint8_t* as = sm8 + buf * STAGE8;
        uint8_t* bs = as + TILE8_BYTES;
        #pragma unroll
        for (int i = 0; i < 2; i++) {
            int ch = t + 256 * i;
            int r = ch >> 2;
            int cc = (ch & 3) * 16;
            cp16(smem_u32(as + r * A8_STRIDE + cc),
                 g_Af8 + (size_t)(m0 + r) * HID_ + k0 + cc);
        }
        #pragma unroll
        for (int i = 0; i < 2; i++) {
            int ch = t + 256 * i;
            int r = ch >> 2;
            int cc = (ch & 3) * 16;
            cp16(smem_u32(bs + r * A8_STRIDE + cc),
                 g_WTf8 + (size_t)(n0 + r) * HID_ + k0 + cc);
        }
        CP_COMMIT();
    };

    load_tile(0, 0);
    load_tile(1, 64);
    load_tile(2, 128);

    const int a_row  = lane & 15;
    const int a_coff = (lane >> 4) * 16;
    const int b_row  = (lane & 7) + 8 * (lane >> 4);
    const int b_coff = 16 * ((lane >> 3) & 1);

    for (int kt = 0; kt < 12; kt++) {
        const int buf = kt & 3;
        CP_WAIT2();
        __syncthreads();
        if (kt + 3 < 12) load_tile((kt + 3) & 3, (kt + 3) * 64);
        else             CP_COMMIT();   // keep group count uniform for WAIT2

        const uint8_t* as = sm8 + buf * STAGE8;
        const uint8_t* bs = as + TILE8_BYTES;

        #pragma unroll
        for (int kk = 0; kk < 2; kk++) {
            const int k32 = kk * 32;
            uint32_t af[2][4];
            #pragma unroll
            for (int mt = 0; mt < 2; mt++) {
                int row = wm * 32 + mt * 16 + a_row;
                ldsm_x4(af[mt], as + row * A8_STRIDE + k32 + a_coff);
            }
            #pragma unroll
            for (int nt = 0; nt < 4; nt++) {
                uint32_t bf[4];
                int row = wn * 64 + nt * 16 + b_row;
                ldsm_x4(bf, bs + row * A8_STRIDE + k32 + b_coff);
                mma_fp8(acc[0][2 * nt],     af[0], &bf[0]);
                mma_fp8(acc[0][2 * nt + 1], af[0], &bf[2]);
                mma_fp8(acc[1][2 * nt],     af[1], &bf[0]);
                mma_fp8(acc[1][2 * nt + 1], af[1], &bf[2]);
            }
        }
    }

    // Epilogue: bias + RoPE + e4m3 scatter to g_q8/g_k8 ([b*h][l][d])
    #pragma unroll
    for (int mt = 0; mt < 2; mt++) {
        #pragma unroll
        for (int half = 0; half < 2; half++) {
            const int m  = m0 + wm * 32 + mt * 16 + g + half * 8;
            const int l  = m & (LL_ - 1);
            const int b_ = m >> 9;
            #pragma unroll
            for (int j = 0; j < 8; j++) {
                const int n = n0 + wn * 64 + j * 8 + 2 * tig;   // even col
                float e = acc[mt][j][half * 2 + 0] + bias[n];
                float o = acc[mt][j][half * 2 + 1] + bias[n + 1];
                const int h  = n >> 7;
                const int qk = (n >> 6) & 1;
                const int d  = n & 63;
                const int p  = d >> 1;
                const float s  = g_sin[l * 32 + p];
                const float co = g_cos[l * 32 + p];
                uint16_t v = f2e4m3x2(e * s + o * co, e * co - o * s);
                uint8_t* dst = (qk ? g_k8 : g_q8)
                    + ((size_t)(b_ * HEADS_ + h) * LL_ + l) * HS_ + d;
                *(uint16_t*)dst = v;
            }
        }
    }
}

// ---------------------------------------------------------------------------
// Kernel 2: logits = (q.k)/8, masked; fp8 mma, ROW-PERSISTENT blocks.
// Block (tm, bh): fills tn<tm, computes tn=tm..7 with double-buffered K.
// Inner fragment/mma/epilogue code identical to R5 (measured-good).
// ---------------------------------------------------------------------------
#define QK8_STRIDE 80

__global__ void __launch_bounds__(128)
attn_logits_fp8(const int* __restrict__ am, float* __restrict__ out) {
    const int tm = blockIdx.x;        // 0..7
    const int bh = blockIdx.y;        // 0..95
    const int t  = threadIdx.x;
    const int b_ = bh / HEADS_;
    const int m0 = tm * 64;
    float* obase = out + (size_t)bh * LL_ * LL_;

    __shared__ uint8_t Qs[64 * QK8_STRIDE];
    __shared__ uint8_t Ks[2][64 * QK8_STRIDE];
    __shared__ int amrow[LL_];

    const uint8_t* qb = g_q8 + ((size_t)bh * LL_ + m0) * HS_;
    const uint8_t* kb = g_k8 + ((size_t)bh * LL_ + tm * 64) * HS_;   // first K tile = tn=tm

    // Stage Q and first K tile
    #pragma unroll
    for (int i = 0; i < 2; i++) {
        int ch = t + 128 * i;
        int r = ch >> 2;
        int c = (ch & 3) * 16;
        cp16(smem_u32(&Qs[r * QK8_STRIDE + c]), qb + r * HS_ + c);
        cp16(smem_u32(&Ks[0][r * QK8_STRIDE + c]), kb + r * HS_ + c);
    }
    CP_COMMIT();
    #pragma unroll
    for (int i = 0; i < 4; i++) amrow[t + 128 * i] = am[b_ * LL_ + t + 128 * i];

    // Below-diagonal fills overlap the in-flight loads
    {
        const float4 nv = make_float4(NEG_INF_F, NEG_INF_F, NEG_INF_F, NEG_INF_F);
        for (int tn = 0; tn < tm; tn++) {
            const int n0 = tn * 64;
            #pragma unroll
            for (int i = t; i < 1024; i += 128) {
                int r = i >> 4;
                int c = (i & 15) * 4;
                stg_cs_f4(&obase[(size_t)(m0 + r) * LL_ + n0 + c], nv);
            }
        }
    }

    CP_WAIT0();
    __syncthreads();

    const int lane = t & 31;
    const int warp = t >> 5;
    const int g    = lane >> 2;
    const int tig  = lane & 3;
    const int wm   = warp >> 1;
    const int wn   = warp & 1;

    const int a_row  = lane & 15;
    const int a_coff = (lane >> 4) * 16;
    const int b_row  = (lane & 7) + 8 * (lane >> 4);
    const int b_coff = 16 * ((lane >> 3) & 1);

    // Hoist Q fragments once (reused for every tn)
    uint32_t qf[2][4];
    #pragma unroll
    for (int mt = 0; mt < 2; mt++) {
        int row = wm * 32 + mt * 16 + a_row;
        ldsm_x4(qf[mt], &Qs[row * QK8_STRIDE + a_coff]);        // k32=0
    }
    uint32_t qf2[2][4];
    #pragma unroll
    for (int mt = 0; mt < 2; mt++) {
        int row = wm * 32 + mt * 16 + a_row;
        ldsm_x4(qf2[mt], &Qs[row * QK8_STRIDE + 32 + a_coff]);  // k32=32
    }

    int buf = 0;
    for (int tn = tm; tn < 8; tn++) {
        // Prefetch next K tile into the other buffer
        if (tn + 1 < 8) {
            const uint8_t* kn = g_k8 + ((size_t)bh * LL_ + (tn + 1) * 64) * HS_;
            #pragma unroll
            for (int i = 0; i < 2; i++) {
                int ch = t + 128 * i;
                int r = ch >> 2;
                int c = (ch & 3) * 16;
                cp16(smem_u32(&Ks[buf ^ 1][r * QK8_STRIDE + c]), kn + r * HS_ + c);
            }
            CP_COMMIT();
        }

        const int n0 = tn * 64;
        float acc[2][4][4];
        #pragma unroll
        for (int mt = 0; mt < 2; mt++)
            #pragma unroll
            for (int j = 0; j < 4; j++)
                #pragma unroll
                for (int c = 0; c < 4; c++) acc[mt][j][c] = 0.0f;

        #pragma unroll
        for (int nt = 0; nt < 2; nt++) {
            uint32_t kf[4];
            int row = wn * 32 + nt * 16 + b_row;
            ldsm_x4(kf, &Ks[buf][row * QK8_STRIDE + b_coff]);           // k32=0
            mma_fp8(acc[0][2 * nt],     qf[0], &kf[0]);
            mma_fp8(acc[0][2 * nt + 1], qf[0], &kf[2]);
            mma_fp8(acc[1][2 * nt],     qf[1], &kf[0]);
            mma_fp8(acc[1][2 * nt + 1], qf[1], &kf[2]);
            ldsm_x4(kf, &Ks[buf][row * QK8_STRIDE + 32 + b_coff]);      // k32=32
            mma_fp8(acc[0][2 * nt],     qf2[0], &kf[0]);
            mma_fp8(acc[0][2 * nt + 1], qf2[0], &kf[2]);
            mma_fp8(acc[1][2 * nt],     qf2[1], &kf[0]);
            mma_fp8(acc[1][2 * nt + 1], qf2[1], &kf[2]);
        }

        // Epilogue: scale, mask, streaming store
        const bool diag = (tn == tm);
        #pragma unroll
        for (int mt = 0; mt < 2; mt++) {
            #pragma unroll
            for (int half = 0; half < 2; half++) {
                const int mi = wm * 32 + mt * 16 + g + half * 8;
                const int m  = m0 + mi;
                const bool rok = (amrow[m] != 0);
                #pragma unroll
                for (int j = 0; j < 4; j++) {
                    const int ni = wn * 32 + j * 8 + 2 * tig;
                    const int n  = n0 + ni;
                    float x0 = acc[mt][j][half * 2 + 0] * 0.125f;
                    float x1 = acc[mt][j][half * 2 + 1] * 0.125f;
                    bool k0 = !rok || amrow[n] == 0;
                    bool k1 = !rok || amrow[n + 1] == 0;
                    if (diag) { k0 |= (m > n); k1 |= (m > n + 1); }
                    if (k0) x0 = NEG_INF_F;
                    if (k1) x1 = NEG_INF_F;
                    stg_cs_f2(&obase[(size_t)m * LL_ + n], x0, x1);
                }
            }
        }

        if (tn + 1 < 8) {
            CP_WAIT0();
            __syncthreads();
        }
        buf ^= 1;
    }
}

// ---------------------------------------------------------------------------
// Entry point
// ---------------------------------------------------------------------------
extern "C" void kernel_launch(void* const* d_in, const int* in_sizes, int n_in,
                              void* d_out, int out_size) {
    const float* inputs = (const float*)d_in[0];  // [8,512,768]
    const float* W      = (const float*)d_in[1];  // [768,1536]
    const float* bias   = (const float*)d_in[2];  // [1536]
    const int*   amask  = (const int*)d_in[3];    // [8,512]
    float* out = (float*)d_out;                   // [8,12,512,512]

    cudaFuncSetAttribute(gemm1_fp8,
                         cudaFuncAttributeMaxDynamicSharedMemorySize, G1_DSMEM);

    prep_all<<<NAB_ + NTB_ + NTRB_, 256>>>(inputs, W);
    gemm1_fp8<<<dim3(OD_ / 128, M1_ / 128), 256, G1_DSMEM>>>(bias);
    attn_logits_fp8<<<dim3(LL_ / 64, BH_), 128>>>(amask, out);
}